// round 16
// baseline (speedup 1.0000x reference)
// HRALinear on GB300 (compute_103 non-'a' toolchain => NO tcgen05/TMA).
// Compact-WY Householder prep + Ampere-style tf32 mma.sync GEMM.
//
// R16: A-operand bypasses shared memory. R15 audit: crossbar 1500 cyc vs
// tensor 1024 per SM-chunk (A+B frag reads both 2x-duplicated + stage
// writes) -> 68% ceiling, exactly measured. Now A fragments are direct
// LDG.64 from g_Xr (K-permuted [0,4,1,5,2,6,3,7] per 8-group, row-major;
// one 8B load per row-pair, 4 coalesced sectors/warp-instr, L2-hot across
// the 32 CTAs sharing a grid-row), register-pipelined one kk ahead
// (covers L2 hit ~250cyc). B keeps cp.async + Latin-swizzle LDS.64, now
// 4 stages (16KB/stage). Crossbar/SM-chunk 192KB -> 96KB (750 cyc < 1024
// tensor) => tensor-bound. rel_err canary: must stay 2.935996e-4.

#include <cuda_runtime.h>
#include <cstdint>

#define DIN  4096
#define DOUT 4096
#define RNK  8
#define MTOT 8192   // 4 * 2048 rows of x

// ---- static device scratch (allocation-free) ----
__device__ float g_UT[RNK * DIN];            // normalized u^T [8][4096]
__device__ float g_G[64];                    // Gram matrix
__device__ float g_T[64];                    // WY T matrix
__device__ float g_Wp[(size_t)DOUT * DIN];   // W' (tf32-rounded, Latin-swizzled)
__device__ float g_Xr[(size_t)MTOT * DIN];   // x  (tf32-rounded, K-pair permuted)

// ============================ helpers ============================

static __device__ __forceinline__ uint32_t smem_u32(const void* p) {
    uint32_t a;
    asm("{ .reg .u64 t; cvta.to.shared.u64 t, %1; cvt.u32.u64 %0, t; }"
        : "=r"(a) : "l"(p));
    return a;
}

static __device__ __forceinline__ float tf32rf(float f) {
    uint32_t u;
    asm("cvt.rna.tf32.f32 %0, %1;" : "=r"(u) : "f"(f));
    return __uint_as_float(u);
}

// ============================ P0: round x to tf32 + K-pair permute ============================
// Within each 8-float K-group store order [0,4,1,5,2,6,3,7]: thread tig's
// mma pair (k=tig, tig+4) sits at bytes 8*tig.. -> one LDG.64 in the GEMM.

__global__ void __launch_bounds__(256)
p0_round(const float* __restrict__ x) {
    size_t i = ((size_t)blockIdx.x * 256 + threadIdx.x) * 4;
    float4 v = *(const float4*)(x + i);
    float* o = g_Xr + (i & ~(size_t)7) + ((i & 4) >> 2);
    o[0] = tf32rf(v.x);
    o[2] = tf32rf(v.y);
    o[4] = tf32rf(v.z);
    o[6] = tf32rf(v.w);
}

// ============================ P1a: normalize u columns (8 blocks) ============================

__global__ void __launch_bounds__(256)
p1a_norm(const float* __restrict__ hu) {
    __shared__ float s_part[8];
    const int i = blockIdx.x;                 // column 0..7
    const int tid = threadIdx.x, wid = tid >> 5, lid = tid & 31;

    float s = 0.f;
    for (int k = tid; k < DIN; k += 256) {
        float v = hu[(size_t)k * RNK + i];
        s += v * v;
    }
    #pragma unroll
    for (int o = 16; o; o >>= 1) s += __shfl_xor_sync(0xFFFFFFFFu, s, o);
    if (lid == 0) s_part[wid] = s;
    __syncthreads();
    if (tid == 0) {
        float t = 0.f;
        #pragma unroll
        for (int w = 0; w < 8; w++) t += s_part[w];
        s_part[0] = rsqrtf(t);
    }
    __syncthreads();
    const float rn = s_part[0];
    for (int k = tid; k < DIN; k += 256)
        g_UT[i * DIN + k] = hu[(size_t)k * RNK + i] * rn;
}

// ============================ P1b: Gram pairs (36 blocks, 1 warp) ============================

__global__ void __launch_bounds__(32)
p1b_gram() {
    const int p = blockIdx.x;                 // pair index 0..35
    int i = 0, rem = p;
    while (rem >= RNK - i) { rem -= RNK - i; i++; }
    const int jj = i + rem;
    const int lid = threadIdx.x;

    float s = 0.f;
    for (int k = lid * 4; k < DIN; k += 128) {
        float4 a4 = *(const float4*)(g_UT + i * DIN + k);
        float4 b4 = *(const float4*)(g_UT + jj * DIN + k);
        s += a4.x * b4.x + a4.y * b4.y + a4.z * b4.z + a4.w * b4.w;
    }
    #pragma unroll
    for (int o = 16; o; o >>= 1) s += __shfl_xor_sync(0xFFFFFFFFu, s, o);
    if (lid == 0) { g_G[i * 8 + jj] = s; g_G[jj * 8 + i] = s; }
}

// ============================ P1c: WY T matrix (1 thread) ============================

__global__ void p1c_buildT() {
    if (threadIdx.x != 0 || blockIdx.x != 0) return;
    float T[64];
    #pragma unroll
    for (int m = 0; m < 64; m++) T[m] = 0.f;
    T[0] = 2.f;
    for (int k = 1; k < 8; k++) {
        for (int i = 0; i < k; i++) {
            float s = 0.f;
            for (int m2 = i; m2 < k; m2++) s += T[i * 8 + m2] * g_G[m2 * 8 + k];
            T[i * 8 + k] = -2.f * s;
        }
        T[k * 8 + k] = 2.f;
    }
    for (int m = 0; m < 64; m++) g_T[m] = T[m];
}

// ============================ P2: W' = W - (W U) T U^T ============================

static constexpr int P2_SMEM = (RNK * DIN + 64) * 4;

__global__ void __launch_bounds__(256)
p2_kernel(const float* __restrict__ W) {
    extern __shared__ float s[];
    float* sUT = s;
    float* sT  = s + RNK * DIN;
    const int tid = threadIdx.x;

    for (int idx = tid * 4; idx < RNK * DIN; idx += 256 * 4)
        *(float4*)(sUT + idx) = *(const float4*)(g_UT + idx);
    if (tid < 64) sT[tid] = g_T[tid];
    __syncthreads();

    const int wid = tid >> 5, lid = tid & 31;
    const int j = blockIdx.x * 8 + wid;          // one W row per warp
    const float* wr = W + (size_t)j * DIN;
    const int rm = j & 3;

    float acc[8] = {0.f, 0.f, 0.f, 0.f, 0.f, 0.f, 0.f, 0.f};
    for (int k = lid * 4; k < DIN; k += 128) {
        float4 w4 = *(const float4*)(wr + k);
        #pragma unroll
        for (int i = 0; i < 8; i++) {
            float4 u4 = *(const float4*)(sUT + i * DIN + k);
            acc[i] += w4.x * u4.x + w4.y * u4.y + w4.z * u4.z + w4.w * u4.w;
        }
    }
    #pragma unroll
    for (int o = 16; o; o >>= 1) {
        #pragma unroll
        for (int i = 0; i < 8; i++)
            acc[i] += __shfl_xor_sync(0xFFFFFFFFu, acc[i], o);
    }
    float v[8];
    #pragma unroll
    for (int i = 0; i < 8; i++) {
        float sv = 0.f;
        #pragma unroll
        for (int m = 0; m < 8; m++) sv += acc[m] * sT[m * 8 + i];
        v[i] = sv;
    }

    float* wp = g_Wp + (size_t)j * DIN;
    for (int k = lid * 4; k < DIN; k += 128) {
        float4 w4 = *(const float4*)(wr + k);
        #pragma unroll
        for (int i = 0; i < 8; i++) {
            float4 u4 = *(const float4*)(sUT + i * DIN + k);
            w4.x -= v[i] * u4.x; w4.y -= v[i] * u4.y;
            w4.z -= v[i] * u4.z; w4.w -= v[i] * u4.w;
        }
        // tf32-RN round + Latin-square swizzled scatter (B smem layout)
        const int kk = (k >> 3) & 3;
        const int q  = (k >> 2) & 1;
        const int p  = (kk + rm) & 3;
        float* o = wp + (k & ~31) + p * 8 + q;
        o[0] = tf32rf(w4.x);
        o[2] = tf32rf(w4.y);
        o[4] = tf32rf(w4.z);
        o[6] = tf32rf(w4.w);
    }
}

// ============================ GEMM: out = Xr @ Wp^T + bias ============================

static constexpr int BM = 128, BN = 128, BK = 32, STG = 4;
static constexpr int ROWF    = 32;                  // B row stride (floats)
static constexpr int BS_F    = BN * ROWF;           // B stage: 4096 floats = 16KB
static constexpr int GEMM_SMEM = STG * BS_F * 4;    // 65536 B (2 CTAs/SM)

// One B stage: 128 rows x 32 floats, 128 threads, 8 x 16B cp.async each.
static __device__ __forceinline__ void issue_stage(const float* gB, int kc,
                                                   int s, uint32_t sb, int tid) {
    uint32_t base = sb + (uint32_t)s * (BS_F * 4);
    #pragma unroll
    for (int j = 0; j < 8; j++) {
        int idx = tid + j * 128;
        int r = idx >> 3, c = idx & 7;
        uint32_t dB = base + (uint32_t)(r * (ROWF * 4) + c * 16);
        const float* sB = gB + (size_t)r * DIN + kc + c * 4;
        asm volatile("cp.async.cg.shared.global [%0], [%1], 16;"
                     :: "r"(dB), "l"(sB));
    }
}

#define MMA4(D, a0, a1, a2, a3, b0, b1) \
    asm volatile("mma.sync.aligned.m16n8k8.row.col.f32.tf32.tf32.f32 " \
                 "{%0,%1,%2,%3}, {%4,%5,%6,%7}, {%8,%9}, {%0,%1,%2,%3};" \
                 : "+f"((D)[0]), "+f"((D)[1]), "+f"((D)[2]), "+f"((D)[3]) \
                 : "r"(a0), "r"(a1), "r"(a2), "r"(a3), "r"(b0), "r"(b1))

// A fragments for one kk-step: 4 mi x 2 row-halves, each one LDG.64.
#define LOAD_A(cc, kk, buf) do {                                             \
    const float* pa_ = pA + (cc) * 32 + (kk) * 8;                            \
    _Pragma("unroll")                                                        \
    for (int mi = 0; mi < 4; mi++) {                                         \
        aB[buf][mi][0] = *(const uint2*)(pa_ + (size_t)(mi * 16) * DIN);     \
        aB[buf][mi][1] = *(const uint2*)(pa_ + (size_t)(mi * 16 + 8) * DIN); \
    }                                                                        \
} while (0)

// B fragments for one kk-step from Latin-swizzled smem stage: 8 LDS.64.
#define LOAD_BF(Bs, kk, buf) do {                                            \
    const int cb_ = (((kk) + rm4) & 3) * 8 + 2 * tig;                        \
    _Pragma("unroll")                                                        \
    for (int ni = 0; ni < 8; ni++) {                                         \
        const int n_ = wn * 64 + ni * 8 + g;                                 \
        float2 fb_ = *(const float2*)((Bs) + n_ * ROWF + cb_);               \
        bB[buf][ni][0] = __float_as_uint(fb_.x);                             \
        bB[buf][ni][1] = __float_as_uint(fb_.y);                             \
    }                                                                        \
} while (0)

__global__ void __launch_bounds__(128, 2)
gemm_tf32(const float* __restrict__ bias, float* __restrict__ out) {
    extern __shared__ float smf[];
    const uint32_t sb = smem_u32(smf);
    const int tid = threadIdx.x, lane = tid & 31, warp = tid >> 5;
    const int g = lane >> 2, tig = lane & 3;
    const int rm4 = g & 3;
    const int wm = warp >> 1, wn = warp & 1;        // 2 x 2 warp grid
    const int m0 = blockIdx.y * BM, n0 = blockIdx.x * BN;

    const float* pA = g_Xr + (size_t)(m0 + wm * 64 + g) * DIN + 2 * tig;
    const float* gB = g_Wp + (size_t)n0 * DIN;

    issue_stage(gB, 0, 0, sb, tid);
    asm volatile("cp.async.commit_group;" ::: "memory");
    issue_stage(gB, BK, 1, sb, tid);
    asm volatile("cp.async.commit_group;" ::: "memory");
    issue_stage(gB, 2 * BK, 2, sb, tid);
    asm volatile("cp.async.commit_group;" ::: "memory");

    float acc[4][8][4];                             // 64x64 warp tile
    #pragma unroll
    for (int mi = 0; mi < 4; mi++)
        #pragma unroll
        for (int ni = 0; ni < 8; ni++)
            #pragma unroll
            for (int q = 0; q < 4; q++) acc[mi][ni][q] = 0.f;

    uint2    aB[2][4][2];                           // A frags, per-kk double buffer
    uint32_t bB[2][8][2];                           // B frags, per-kk double buffer

    LOAD_A(0, 0, 0);                                // prologue: chunk0 kk0

    const int NCH = DIN / BK;                       // 128 K-chunks
    for (int c = 0; c < NCH; c++) {
        asm volatile("cp.async.wait_group 2;" ::: "memory");
        __syncthreads();

        const float* Bs = smf + (c % STG) * BS_F;
        LOAD_BF(Bs, 0, 0);                          // B kk0 (needs this stage)

        if (c + 3 < NCH) issue_stage(gB, (c + 3) * BK, (c + 3) % STG, sb, tid);
        asm volatile("cp.async.commit_group;" ::: "memory");

        const int cnext = (c + 1 < NCH) ? c + 1 : 0;  // clamp (dummy reload)
        #pragma unroll
        for (int kk = 0; kk < 4; kk++) {
            const int cur = kk & 1, nxt = cur ^ 1;
            if (kk < 3) {                            // prefetch next kk
                LOAD_A(c, kk + 1, nxt);
                LOAD_BF(Bs, kk + 1, nxt);
            } else {                                 // cross-chunk A prefetch
                LOAD_A(cnext, 0, nxt);
            }
            #pragma unroll
            for (int mi = 0; mi < 4; mi++)
                #pragma unroll
                for (int ni = 0; ni < 8; ni++)
                    MMA4(acc[mi][ni],
                         aB[cur][mi][0].x, aB[cur][mi][1].x,
                         aB[cur][mi][0].y, aB[cur][mi][1].y,
                         bB[cur][ni][0], bB[cur][ni][1]);
        }
    }

    // Epilogue: direct STG.64 per (row, 2-col) pair + bias.
    #pragma unroll
    for (int mi = 0; mi < 4; mi++) {
        const int row = m0 + wm * 64 + mi * 16 + g;
        #pragma unroll
        for (int ni = 0; ni < 8; ni++) {
            const int col = n0 + wn * 64 + ni * 8 + 2 * tig;
            const float2 bv = *(const float2*)(bias + col);
            float2 o0, o1;
            o0.x = acc[mi][ni][0] + bv.x; o0.y = acc[mi][ni][1] + bv.y;
            o1.x = acc[mi][ni][2] + bv.x; o1.y = acc[mi][ni][3] + bv.y;
            *(float2*)(out + (size_t)row * DOUT + col) = o0;
            *(float2*)(out + (size_t)(row + 8) * DOUT + col) = o1;
        }
    }
}

// ============================ launch ============================

extern "C" void kernel_launch(void* const* d_in, const int* in_sizes, int n_in,
                              void* d_out, int out_size) {
    const float* x    = (const float*)d_in[0];  // [4, 2048, 4096]
    const float* hu   = (const float*)d_in[1];  // [4096, 8]
    const float* W    = (const float*)d_in[2];  // [4096, 4096]
    const float* bias = (const float*)d_in[3];  // [4096]
    float* out = (float*)d_out;                 // [4, 2048, 4096]
    (void)in_sizes; (void)n_in; (void)out_size;

    cudaFuncSetAttribute(p2_kernel, cudaFuncAttributeMaxDynamicSharedMemorySize, P2_SMEM);
    cudaFuncSetAttribute(gemm_tf32, cudaFuncAttributeMaxDynamicSharedMemorySize, GEMM_SMEM);

    p0_round<<<(MTOT * DIN) / (256 * 4), 256>>>(x);
    p1a_norm<<<8, 256>>>(hu);
    p1b_gram<<<36, 32>>>();
    p1c_buildT<<<1, 32>>>();
    p2_kernel<<<512, 256, P2_SMEM>>>(W);
    gemm_tf32<<<dim3(DOUT / BN, MTOT / BM), 128, GEMM_SMEM>>>(bias, out);
}

// round 17
// speedup vs baseline: 1.3753x; 1.3753x over previous
// HRALinear on GB300 (compute_103 non-'a' toolchain => NO tcgen05/TMA).
// Compact-WY Householder prep + Ampere-style tf32 mma.sync GEMM.
//
// R17: A-direct-from-global, take 2. R16 died on L1tex wavefronts: each
// LDG.64 fragment spanned 8 rows = 8 lines = 8 wavefronts (2048 cyc/SM-
// chunk > 1024 MMA floor). Now g_Xr is FRAGMENT-MAJOR: P0 stores each
// (16-row tile T, 8-k frag F) as the exact 512B the warp wants -> one
// LDG.128 per fragment, 4 wavefronts (minimal). Per SM-chunk: A = 512
// wf-cyc on L1tex, B = 750 cyc on crossbar, MMA = 1024 cyc -> tensor-
// bound. B path unchanged from R15 (cp.async + Latin-swizzle LDS.64,
// 4 stages, 2 CTAs/SM). rel_err canary: must stay 2.935996e-4.

#include <cuda_runtime.h>
#include <cstdint>

#define DIN  4096
#define DOUT 4096
#define RNK  8
#define MTOT 8192   // 4 * 2048 rows of x

// ---- static device scratch (allocation-free) ----
__device__ float g_UT[RNK * DIN];            // normalized u^T [8][4096]
__device__ float g_G[64];                    // Gram matrix
__device__ float g_T[64];                    // WY T matrix
__device__ float g_Wp[(size_t)DOUT * DIN];   // W' (tf32-rounded, Latin-swizzled)
__device__ float g_Xr[(size_t)MTOT * DIN];   // x  (tf32-rounded, FRAGMENT-major)

// ============================ helpers ============================

static __device__ __forceinline__ uint32_t smem_u32(const void* p) {
    uint32_t a;
    asm("{ .reg .u64 t; cvta.to.shared.u64 t, %1; cvt.u32.u64 %0, t; }"
        : "=r"(a) : "l"(p));
    return a;
}

static __device__ __forceinline__ float tf32rf(float f) {
    uint32_t u;
    asm("cvt.rna.tf32.f32 %0, %1;" : "=r"(u) : "f"(f));
    return __uint_as_float(u);
}

// ============================ P0: round x to tf32, fragment-major scatter ============================
// Fragment (T = m>>4, F = k>>3) is 128 floats: lane l = 4g+tig holds
// [a0,a1,a2,a3] = [(g,tig),(g+8,tig),(g,tig+4),(g+8,tig+4)] at l*4.
// Value (ri = m&15, ki = k&7): g = ri&7, half = ri>>3, q = ki>>2,
// tig = ki&3 -> pos = 16g + 4*tig + 2q + half.

__global__ void __launch_bounds__(256)
p0_round(const float* __restrict__ x) {
    size_t i = ((size_t)blockIdx.x * 256 + threadIdx.x) * 4;
    float4 v = *(const float4*)(x + i);
    const int m  = (int)(i >> 12);
    const int k  = (int)(i & 4095);
    const int T  = m >> 4, ri = m & 15;
    const int F  = k >> 3, q = (k >> 2) & 1;
    const int gg = ri & 7, half = ri >> 3;
    float* o = g_Xr + ((size_t)T * 512 + F) * 128 + 16 * gg + 2 * q + half;
    o[0]  = tf32rf(v.x);      // tig = 0
    o[4]  = tf32rf(v.y);      // tig = 1
    o[8]  = tf32rf(v.z);      // tig = 2
    o[12] = tf32rf(v.w);      // tig = 3
}

// ============================ P1a: normalize u columns (8 blocks) ============================

__global__ void __launch_bounds__(256)
p1a_norm(const float* __restrict__ hu) {
    __shared__ float s_part[8];
    const int i = blockIdx.x;                 // column 0..7
    const int tid = threadIdx.x, wid = tid >> 5, lid = tid & 31;

    float s = 0.f;
    for (int k = tid; k < DIN; k += 256) {
        float v = hu[(size_t)k * RNK + i];
        s += v * v;
    }
    #pragma unroll
    for (int o = 16; o; o >>= 1) s += __shfl_xor_sync(0xFFFFFFFFu, s, o);
    if (lid == 0) s_part[wid] = s;
    __syncthreads();
    if (tid == 0) {
        float t = 0.f;
        #pragma unroll
        for (int w = 0; w < 8; w++) t += s_part[w];
        s_part[0] = rsqrtf(t);
    }
    __syncthreads();
    const float rn = s_part[0];
    for (int k = tid; k < DIN; k += 256)
        g_UT[i * DIN + k] = hu[(size_t)k * RNK + i] * rn;
}

// ============================ P1b: Gram pairs (36 blocks, 1 warp) ============================

__global__ void __launch_bounds__(32)
p1b_gram() {
    const int p = blockIdx.x;                 // pair index 0..35
    int i = 0, rem = p;
    while (rem >= RNK - i) { rem -= RNK - i; i++; }
    const int jj = i + rem;
    const int lid = threadIdx.x;

    float s = 0.f;
    for (int k = lid * 4; k < DIN; k += 128) {
        float4 a4 = *(const float4*)(g_UT + i * DIN + k);
        float4 b4 = *(const float4*)(g_UT + jj * DIN + k);
        s += a4.x * b4.x + a4.y * b4.y + a4.z * b4.z + a4.w * b4.w;
    }
    #pragma unroll
    for (int o = 16; o; o >>= 1) s += __shfl_xor_sync(0xFFFFFFFFu, s, o);
    if (lid == 0) { g_G[i * 8 + jj] = s; g_G[jj * 8 + i] = s; }
}

// ============================ P1c: WY T matrix (1 thread) ============================

__global__ void p1c_buildT() {
    if (threadIdx.x != 0 || blockIdx.x != 0) return;
    float T[64];
    #pragma unroll
    for (int m = 0; m < 64; m++) T[m] = 0.f;
    T[0] = 2.f;
    for (int k = 1; k < 8; k++) {
        for (int i = 0; i < k; i++) {
            float s = 0.f;
            for (int m2 = i; m2 < k; m2++) s += T[i * 8 + m2] * g_G[m2 * 8 + k];
            T[i * 8 + k] = -2.f * s;
        }
        T[k * 8 + k] = 2.f;
    }
    for (int m = 0; m < 64; m++) g_T[m] = T[m];
}

// ============================ P2: W' = W - (W U) T U^T ============================

static constexpr int P2_SMEM = (RNK * DIN + 64) * 4;

__global__ void __launch_bounds__(256)
p2_kernel(const float* __restrict__ W) {
    extern __shared__ float s[];
    float* sUT = s;
    float* sT  = s + RNK * DIN;
    const int tid = threadIdx.x;

    for (int idx = tid * 4; idx < RNK * DIN; idx += 256 * 4)
        *(float4*)(sUT + idx) = *(const float4*)(g_UT + idx);
    if (tid < 64) sT[tid] = g_T[tid];
    __syncthreads();

    const int wid = tid >> 5, lid = tid & 31;
    const int j = blockIdx.x * 8 + wid;          // one W row per warp
    const float* wr = W + (size_t)j * DIN;
    const int rm = j & 3;

    float acc[8] = {0.f, 0.f, 0.f, 0.f, 0.f, 0.f, 0.f, 0.f};
    for (int k = lid * 4; k < DIN; k += 128) {
        float4 w4 = *(const float4*)(wr + k);
        #pragma unroll
        for (int i = 0; i < 8; i++) {
            float4 u4 = *(const float4*)(sUT + i * DIN + k);
            acc[i] += w4.x * u4.x + w4.y * u4.y + w4.z * u4.z + w4.w * u4.w;
        }
    }
    #pragma unroll
    for (int o = 16; o; o >>= 1) {
        #pragma unroll
        for (int i = 0; i < 8; i++)
            acc[i] += __shfl_xor_sync(0xFFFFFFFFu, acc[i], o);
    }
    float v[8];
    #pragma unroll
    for (int i = 0; i < 8; i++) {
        float sv = 0.f;
        #pragma unroll
        for (int m = 0; m < 8; m++) sv += acc[m] * sT[m * 8 + i];
        v[i] = sv;
    }

    float* wp = g_Wp + (size_t)j * DIN;
    for (int k = lid * 4; k < DIN; k += 128) {
        float4 w4 = *(const float4*)(wr + k);
        #pragma unroll
        for (int i = 0; i < 8; i++) {
            float4 u4 = *(const float4*)(sUT + i * DIN + k);
            w4.x -= v[i] * u4.x; w4.y -= v[i] * u4.y;
            w4.z -= v[i] * u4.z; w4.w -= v[i] * u4.w;
        }
        // tf32-RN round + Latin-square swizzled scatter (B smem layout)
        const int kk = (k >> 3) & 3;
        const int q  = (k >> 2) & 1;
        const int p  = (kk + rm) & 3;
        float* o = wp + (k & ~31) + p * 8 + q;
        o[0] = tf32rf(w4.x);
        o[2] = tf32rf(w4.y);
        o[4] = tf32rf(w4.z);
        o[6] = tf32rf(w4.w);
    }
}

// ============================ GEMM: out = Xr @ Wp^T + bias ============================

static constexpr int BM = 128, BN = 128, BK = 32, STG = 4;
static constexpr int ROWF    = 32;                  // B row stride (floats)
static constexpr int BS_F    = BN * ROWF;           // B stage: 4096 floats = 16KB
static constexpr int GEMM_SMEM = STG * BS_F * 4;    // 65536 B (2 CTAs/SM)

// One B stage: 128 rows x 32 floats, 128 threads, 8 x 16B cp.async each.
static __device__ __forceinline__ void issue_stage(const float* gB, int kc,
                                                   int s, uint32_t sb, int tid) {
    uint32_t base = sb + (uint32_t)s * (BS_F * 4);
    #pragma unroll
    for (int j = 0; j < 8; j++) {
        int idx = tid + j * 128;
        int r = idx >> 3, c = idx & 7;
        uint32_t dB = base + (uint32_t)(r * (ROWF * 4) + c * 16);
        const float* sB = gB + (size_t)r * DIN + kc + c * 4;
        asm volatile("cp.async.cg.shared.global [%0], [%1], 16;"
                     :: "r"(dB), "l"(sB));
    }
}

#define MMA4(D, a0, a1, a2, a3, b0, b1) \
    asm volatile("mma.sync.aligned.m16n8k8.row.col.f32.tf32.tf32.f32 " \
                 "{%0,%1,%2,%3}, {%4,%5,%6,%7}, {%8,%9}, {%0,%1,%2,%3};" \
                 : "+f"((D)[0]), "+f"((D)[1]), "+f"((D)[2]), "+f"((D)[3]) \
                 : "r"(a0), "r"(a1), "r"(a2), "r"(a3), "r"(b0), "r"(b1))

// A fragments for one kk-step: 4 LDG.128 (one per mi), fully coalesced.
#define LOAD_A(cc, kk, buf) do {                                             \
    const size_t offs_ = (size_t)((cc) * 4 + (kk)) * 128;                    \
    _Pragma("unroll")                                                        \
    for (int mi = 0; mi < 4; mi++)                                           \
        aB[buf][mi] = *(const uint4*)(pA0 + (size_t)mi * 65536 + offs_);     \
} while (0)

// B fragments for one kk-step from Latin-swizzled smem stage: 8 LDS.64.
#define LOAD_BF(Bs, kk, buf) do {                                            \
    const int cb_ = (((kk) + rm4) & 3) * 8 + 2 * tig;                        \
    _Pragma("unroll")                                                        \
    for (int ni = 0; ni < 8; ni++) {                                         \
        const int n_ = wn * 64 + ni * 8 + g;                                 \
        float2 fb_ = *(const float2*)((Bs) + n_ * ROWF + cb_);               \
        bB[buf][ni][0] = __float_as_uint(fb_.x);                             \
        bB[buf][ni][1] = __float_as_uint(fb_.y);                             \
    }                                                                        \
} while (0)

__global__ void __launch_bounds__(128, 2)
gemm_tf32(const float* __restrict__ bias, float* __restrict__ out) {
    extern __shared__ float smf[];
    const uint32_t sb = smem_u32(smf);
    const int tid = threadIdx.x, lane = tid & 31, warp = tid >> 5;
    const int g = lane >> 2, tig = lane & 3;
    const int rm4 = g & 3;
    const int wm = warp >> 1, wn = warp & 1;        // 2 x 2 warp grid
    const int m0 = blockIdx.y * BM, n0 = blockIdx.x * BN;

    // Fragment-major A base: tile row (m0/16 + wm*4), lane offset 4 floats.
    const float* pA0 = g_Xr + ((size_t)(m0 / 16 + wm * 4) * 512) * 128 + lane * 4;
    const float* gB = g_Wp + (size_t)n0 * DIN;

    issue_stage(gB, 0, 0, sb, tid);
    asm volatile("cp.async.commit_group;" ::: "memory");
    issue_stage(gB, BK, 1, sb, tid);
    asm volatile("cp.async.commit_group;" ::: "memory");
    issue_stage(gB, 2 * BK, 2, sb, tid);
    asm volatile("cp.async.commit_group;" ::: "memory");

    float acc[4][8][4];                             // 64x64 warp tile
    #pragma unroll
    for (int mi = 0; mi < 4; mi++)
        #pragma unroll
        for (int ni = 0; ni < 8; ni++)
            #pragma unroll
            for (int q = 0; q < 4; q++) acc[mi][ni][q] = 0.f;

    uint4    aB[2][4];                              // A frags, per-kk double buffer
    uint32_t bB[2][8][2];                           // B frags, per-kk double buffer

    LOAD_A(0, 0, 0);                                // prologue: chunk0 kk0

    const int NCH = DIN / BK;                       // 128 K-chunks
    for (int c = 0; c < NCH; c++) {
        asm volatile("cp.async.wait_group 2;" ::: "memory");
        __syncthreads();

        const float* Bs = smf + (c % STG) * BS_F;
        LOAD_BF(Bs, 0, 0);                          // B kk0 (needs this stage)

        if (c + 3 < NCH) issue_stage(gB, (c + 3) * BK, (c + 3) % STG, sb, tid);
        asm volatile("cp.async.commit_group;" ::: "memory");

        const int cnext = (c + 1 < NCH) ? c + 1 : 0;  // clamp (dummy reload)
        #pragma unroll
        for (int kk = 0; kk < 4; kk++) {
            const int cur = kk & 1, nxt = cur ^ 1;
            if (kk < 3) {                            // prefetch next kk
                LOAD_A(c, kk + 1, nxt);
                LOAD_BF(Bs, kk + 1, nxt);
            } else {                                 // cross-chunk A prefetch
                LOAD_A(cnext, 0, nxt);
            }
            #pragma unroll
            for (int mi = 0; mi < 4; mi++)
                #pragma unroll
                for (int ni = 0; ni < 8; ni++)
                    MMA4(acc[mi][ni],
                         aB[cur][mi].x, aB[cur][mi].y,
                         aB[cur][mi].z, aB[cur][mi].w,
                         bB[cur][ni][0], bB[cur][ni][1]);
        }
    }

    // Epilogue: direct STG.64 per (row, 2-col) pair + bias.
    #pragma unroll
    for (int mi = 0; mi < 4; mi++) {
        const int row = m0 + wm * 64 + mi * 16 + g;
        #pragma unroll
        for (int ni = 0; ni < 8; ni++) {
            const int col = n0 + wn * 64 + ni * 8 + 2 * tig;
            const float2 bv = *(const float2*)(bias + col);
            float2 o0, o1;
            o0.x = acc[mi][ni][0] + bv.x; o0.y = acc[mi][ni][1] + bv.y;
            o1.x = acc[mi][ni][2] + bv.x; o1.y = acc[mi][ni][3] + bv.y;
            *(float2*)(out + (size_t)row * DOUT + col) = o0;
            *(float2*)(out + (size_t)(row + 8) * DOUT + col) = o1;
        }
    }
}

// ============================ launch ============================

extern "C" void kernel_launch(void* const* d_in, const int* in_sizes, int n_in,
                              void* d_out, int out_size) {
    const float* x    = (const float*)d_in[0];  // [4, 2048, 4096]
    const float* hu   = (const float*)d_in[1];  // [4096, 8]
    const float* W    = (const float*)d_in[2];  // [4096, 4096]
    const float* bias = (const float*)d_in[3];  // [4096]
    float* out = (float*)d_out;                 // [4, 2048, 4096]
    (void)in_sizes; (void)n_in; (void)out_size;

    cudaFuncSetAttribute(p2_kernel, cudaFuncAttributeMaxDynamicSharedMemorySize, P2_SMEM);
    cudaFuncSetAttribute(gemm_tf32, cudaFuncAttributeMaxDynamicSharedMemorySize, GEMM_SMEM);

    p0_round<<<(MTOT * DIN) / (256 * 4), 256>>>(x);
    p1a_norm<<<8, 256>>>(hu);
    p1b_gram<<<36, 32>>>();
    p1c_buildT<<<1, 32>>>();
    p2_kernel<<<512, 256, P2_SMEM>>>(W);
    gemm_tf32<<<dim3(DOUT / BN, MTOT / BM), 128, GEMM_SMEM>>>(bias, out);
}